// round 12
// baseline (speedup 1.0000x reference)
#include <cuda_runtime.h>
#include <cuda_bf16.h>
#include <math.h>

#define H 1024
#define W 1024
#define OROWS 4                       // output rows per CTA
#define FHALO 3                       // fast-path window radius
#define SROWS (OROWS + 2 * FHALO)     // 10 scan rows per CTA
#define SENT (1 << 30)

__device__ __forceinline__ float sqrt_approx(float x) {
    float r;
    asm("sqrt.approx.f32 %0, %1;" : "=f"(r) : "f"(x));
    return r;
}

// Exact fallback: brute force over all zero pixels. Correct for any input;
// probability of use ~2^-19 per pixel (needs all 7 fast-window rows jointly bad).
__device__ __noinline__ float brute_force_d2(const float* __restrict__ img,
                                             int i, int j) {
    float best = 3.4e38f;
    for (int p = 0; p < H; p++) {
        const float dp = (float)(i - p);
        const float dp2 = dp * dp;
        if (dp2 >= best) continue;
        for (int q = 0; q < W; q++) {
            if (img[p * W + q] == 0.0f) {
                const float dq = (float)(j - q);
                best = fminf(best, dp2 + dq * dq);
            }
        }
    }
    if (best > 1e10f) best = 1e10f;   // no zero anywhere -> reference BIG
    return best;
}

// ---------------------------------------------------------------------------
// Fused EDT. Phase A: warps 0..9 each scan one image row (32 px/lane bitmask
// scan) into u16 smem distances. Phase B: each thread = 2 columns x 4 output
// rows, packed u32 window loads, 7-tap parabola min, m<=9 exact else fallback.
// ---------------------------------------------------------------------------
__global__ void __launch_bounds__(512) edt_fused_kernel(
    const float* __restrict__ img, float* __restrict__ out) {

    __shared__ unsigned short sd[SROWS][W];   // 20 KB

    const int tid = threadIdx.x;
    const int lane = tid & 31;
    const int w = tid >> 5;                   // warp id 0..15
    const int ob = blockIdx.x * OROWS;        // first output row of this CTA

    // ---------------- Phase A: row scans (warps 0..9) ----------------------
    if (w < SROWS) {
        const int srow = ob - FHALO + w;      // global image row
        const int base = lane * 32;           // first pixel owned by lane

        unsigned mask = 0u;
        if (srow >= 0 && srow < H) {
            const float4* __restrict__ i4 =
                (const float4*)(img + srow * W) + lane * 8;
            #pragma unroll
            for (int q = 0; q < 8; q++) {
                const float4 v = i4[q];
                if (v.x == 0.0f) mask |= 1u << (q * 4 + 0);
                if (v.y == 0.0f) mask |= 1u << (q * 4 + 1);
                if (v.z == 0.0f) mask |= 1u << (q * 4 + 2);
                if (v.w == 0.0f) mask |= 1u << (q * 4 + 3);
            }
        }

        // Lane aggregates: last/first zero index in this lane's 32 pixels.
        const int aggL = mask ? (base + 31 - __clz(mask)) : -SENT;
        const int aggR = mask ? (base + __ffs(mask) - 1) : SENT;

        // Cross-lane exclusive carries (all lanes participate in shuffles).
        int a = aggL;
        #pragma unroll
        for (int o = 1; o < 32; o <<= 1) {
            int t = __shfl_up_sync(0xffffffffu, a, o);
            if (lane >= o) a = max(a, t);
        }
        int carryL = __shfl_up_sync(0xffffffffu, a, 1);
        if (lane == 0) carryL = -SENT;

        int b = aggR;
        #pragma unroll
        for (int o = 1; o < 32; o <<= 1) {
            int t = __shfl_down_sync(0xffffffffu, b, o);
            if (lane < 32 - o) b = min(b, t);
        }
        int carryR = __shfl_down_sync(0xffffffffu, b, 1);
        if (lane == 31) carryR = SENT;

        // Per-pixel distances; pack u16 pairs and store 4x uint4.
        unsigned short dv[32];
        #pragma unroll
        for (int p = 0; p < 32; p++) {
            const int idx = base + p;
            const unsigned ml = mask & (0xFFFFFFFFu >> (31 - p));
            const unsigned mr = mask & (0xFFFFFFFFu << p);
            const int zl = ml ? (base + 31 - __clz(ml)) : carryL;
            const int zr = mr ? (base + __ffs(mr) - 1) : carryR;
            const int d = min(idx - zl, zr - idx);
            dv[p] = (unsigned short)min(d, 0xFFFF);
        }
        #pragma unroll
        for (int q = 0; q < 4; q++) {
            uint4 pk;
            pk.x = (unsigned)dv[q * 8 + 0] | ((unsigned)dv[q * 8 + 1] << 16);
            pk.y = (unsigned)dv[q * 8 + 2] | ((unsigned)dv[q * 8 + 3] << 16);
            pk.z = (unsigned)dv[q * 8 + 4] | ((unsigned)dv[q * 8 + 5] << 16);
            pk.w = (unsigned)dv[q * 8 + 6] | ((unsigned)dv[q * 8 + 7] << 16);
            *(uint4*)(&sd[w][base + q * 8]) = pk;
        }
    }
    __syncthreads();

    // ---------------- Phase B: column parabola window ----------------------
    const int j0 = tid * 2;                   // this thread's 2 columns

    float wl[SROWS], wr[SROWS];
    #pragma unroll
    for (int k = 0; k < SROWS; k++) {
        const unsigned pk = *(const unsigned*)(&sd[k][j0]);
        wl[k] = (float)(pk & 0xFFFFu);
        wr[k] = (float)(pk >> 16);
    }

    // Output u (row ob+u) centers at window index u+FHALO.
    float ml[OROWS], mr[OROWS];
    #pragma unroll
    for (int u = 0; u < OROWS; u++) {
        const float cl = wl[u + FHALO];
        const float cr = wr[u + FHALO];
        ml[u] = cl * cl;
        mr[u] = cr * cr;
    }
    #pragma unroll
    for (int d = 1; d <= FHALO; d++) {
        const float dd = (float)(d * d);
        #pragma unroll
        for (int u = 0; u < OROWS; u++) {
            const float a0 = wl[u + FHALO - d], a1 = wl[u + FHALO + d];
            const float b0 = wr[u + FHALO - d], b1 = wr[u + FHALO + d];
            ml[u] = fminf(ml[u], fmaf(a0, a0, dd));
            ml[u] = fminf(ml[u], fmaf(a1, a1, dd));
            mr[u] = fminf(mr[u], fmaf(b0, b0, dd));
            mr[u] = fminf(mr[u], fmaf(b1, b1, dd));
        }
    }

    // m <= 9 => exact (|i-k| >= 4 contributes >= 16 > 9). Else brute force.
    #pragma unroll
    for (int u = 0; u < OROWS; u++) {
        float a = ml[u], b = mr[u];
        if (a > 9.0f) a = brute_force_d2(img, ob + u, j0);
        if (b > 9.0f) b = brute_force_d2(img, ob + u, j0 + 1);
        float2 o2 = make_float2(sqrt_approx(a), sqrt_approx(b));
        *(float2*)(out + (ob + u) * W + j0) = o2;
    }
}

// ---------------------------------------------------------------------------
extern "C" void kernel_launch(void* const* d_in, const int* in_sizes, int n_in,
                              void* d_out, int out_size) {
    const float* img = (const float*)d_in[0];
    float* out = (float*)d_out;
    edt_fused_kernel<<<H / OROWS, 512>>>(img, out);   // 256 CTAs
}

// round 14
// speedup vs baseline: 1.4569x; 1.4569x over previous
#include <cuda_runtime.h>
#include <cuda_bf16.h>
#include <math.h>

#define H 1024
#define W 1024
#define OROWS 8                       // output rows per CTA
#define FHALO 3                       // fast-path window radius
#define SROWS (OROWS + 2 * FHALO)     // 14 scan rows per CTA
#define NTASK (SROWS * 4)             // 56 quarter-row tasks per CTA
#define SMEM_BYTES (SROWS * W * sizeof(float))   // 56 KB dynamic

__device__ __forceinline__ float sqrt_approx(float x) {
    float r;
    asm("sqrt.approx.f32 %0, %1;" : "=f"(r) : "f"(x));
    return r;
}

// Exact fallback: brute force over all zero pixels. Correct for any input;
// fires with probability ~2e-9 per pixel (all 7 fast-window rows jointly bad).
__device__ __noinline__ float brute_force_d2(const float* __restrict__ img,
                                             int i, int j) {
    float best = 3.4e38f;
    for (int p = 0; p < H; p++) {
        const float dp = (float)(i - p);
        const float dp2 = dp * dp;
        if (dp2 >= best) continue;
        for (int q = 0; q < W; q++) {
            if (img[p * W + q] == 0.0f) {
                const float dq = (float)(j - q);
                best = fminf(best, dp2 + dq * dq);
            }
        }
    }
    if (best > 1e10f) best = 1e10f;   // no zero anywhere -> reference BIG
    return best;
}

// ---------------------------------------------------------------------------
// Fused EDT, clamped-local row pass.
// Phase A: 56 quarter-row tasks (14 rows x 4 quarters, 8 px/lane). Row
// distance CLAMPED to 3 (d^2 in {0,1,4,9,16} stored as float) -> purely
// local: 7-bit zero-mask window per pixel, no scans, no carries.
// Phase B: per column, 7-tap parabola min over +-3 rows; m<=9 is provably
// the exact global min, else exact brute-force fallback.
// ---------------------------------------------------------------------------
__global__ void __launch_bounds__(1024) edt_fused_kernel(
    const float* __restrict__ img, float* __restrict__ out) {

    extern __shared__ float sd[];             // [SROWS][W], 56 KB dynamic
    __shared__ unsigned eb_lo[SROWS][4];      // first-3-px zero bits per quarter
    __shared__ unsigned eb_hi[SROWS][4];      // last-3-px zero bits per quarter

    const int tid = threadIdx.x;
    const int lane = tid & 31;
    const int wid = tid >> 5;                 // 0..31
    const int ob = blockIdx.x * OROWS;        // first output row of this CTA

    // -------- Phase A, step 1: load pixels, build 8-bit zero masks ---------
    unsigned msk[2];
    int rownum[2], qnum[2], basepx[2];
    #pragma unroll
    for (int s = 0; s < 2; s++) {
        const int t = wid + s * 32;
        if (t < NTASK) {
            const int r = t >> 2;             // scan row 0..13
            const int q = t & 3;              // quarter 0..3
            const int base = q * 256 + lane * 8;
            const int srow = ob - FHALO + r;  // global image row
            unsigned mk = 0u;
            if (srow >= 0 && srow < H) {
                const float4* __restrict__ i4 =
                    (const float4*)(img + srow * W) + base / 4;
                const float4 v0 = i4[0], v1 = i4[1];
                if (v0.x == 0.0f) mk |= 1u;
                if (v0.y == 0.0f) mk |= 2u;
                if (v0.z == 0.0f) mk |= 4u;
                if (v0.w == 0.0f) mk |= 8u;
                if (v1.x == 0.0f) mk |= 16u;
                if (v1.y == 0.0f) mk |= 32u;
                if (v1.z == 0.0f) mk |= 64u;
                if (v1.w == 0.0f) mk |= 128u;
            }
            msk[s] = mk;
            rownum[s] = r; qnum[s] = q; basepx[s] = base;
            if (lane == 0)  eb_lo[r][q] = mk & 7u;
            if (lane == 31) eb_hi[r][q] = mk >> 5;
        } else {
            rownum[s] = -1; msk[s] = 0u; qnum[s] = 0; basepx[s] = 0;
        }
    }
    __syncthreads();

    // -------- Phase A, step 2: per-pixel clamped distance from 7-bit window -
    #pragma unroll
    for (int s = 0; s < 2; s++) {
        if (rownum[s] >= 0) {                 // warp-uniform branch
            const unsigned mk = msk[s];
            const int r = rownum[s], q = qnum[s], base = basepx[s];

            unsigned p3 = __shfl_up_sync(0xffffffffu, mk, 1) >> 5;
            if (lane == 0) p3 = q ? eb_hi[r][q - 1] : 0u;
            unsigned n3 = __shfl_down_sync(0xffffffffu, mk, 1) & 7u;
            if (lane == 31) n3 = (q < 3) ? eb_lo[r][q + 1] : 0u;

            // ext bit k = zero flag of pixel (base - 3 + k), k = 0..13
            const unsigned ext = p3 | (mk << 3) | (n3 << 11);

            float dv[8];
            #pragma unroll
            for (int p = 0; p < 8; p++) {
                const unsigned wb = (ext >> p) & 0x7Fu;  // bit 3 = center px
                float d2 = 16.0f;                        // d >= 4 (clamped)
                if (wb & 0x41u) d2 = 9.0f;               // d = 3
                if (wb & 0x22u) d2 = 4.0f;               // d = 2
                if (wb & 0x14u) d2 = 1.0f;               // d = 1
                if (wb & 0x08u) d2 = 0.0f;               // d = 0
                dv[p] = d2;
            }
            *(float4*)&sd[r * W + base]     = make_float4(dv[0], dv[1], dv[2], dv[3]);
            *(float4*)&sd[r * W + base + 4] = make_float4(dv[4], dv[5], dv[6], dv[7]);
        }
    }
    __syncthreads();

    // -------- Phase B: column parabola window (1 column per thread) --------
    const int j = tid;

    float wv[SROWS];
    #pragma unroll
    for (int k = 0; k < SROWS; k++) wv[k] = sd[k * W + j];

    float m[OROWS];
    #pragma unroll
    for (int u = 0; u < OROWS; u++) m[u] = wv[u + FHALO];   // d_i = 0 tap
    #pragma unroll
    for (int d = 1; d <= FHALO; d++) {
        const float dd = (float)(d * d);
        #pragma unroll
        for (int u = 0; u < OROWS; u++) {
            m[u] = fminf(m[u], wv[u + FHALO - d] + dd);
            m[u] = fminf(m[u], wv[u + FHALO + d] + dd);
        }
    }

    // m <= 9 => exact: clamped taps are >= 16 and |d_i| >= 4 taps are >= 16,
    // so the winning tap is a true value and dominates everything outside.
    #pragma unroll
    for (int u = 0; u < OROWS; u++) {
        float mv = m[u];
        if (mv > 9.0f) mv = brute_force_d2(img, ob + u, j);
        out[(ob + u) * W + j] = sqrt_approx(mv);
    }
}

// ---------------------------------------------------------------------------
extern "C" void kernel_launch(void* const* d_in, const int* in_sizes, int n_in,
                              void* d_out, int out_size) {
    const float* img = (const float*)d_in[0];
    float* out = (float*)d_out;

    // Deterministic, capture-safe (not a stream op, no allocation).
    cudaFuncSetAttribute(edt_fused_kernel,
                         cudaFuncAttributeMaxDynamicSharedMemorySize,
                         (int)SMEM_BYTES);

    edt_fused_kernel<<<H / OROWS, 1024, SMEM_BYTES>>>(img, out);  // 128 CTAs
}